// round 15
// baseline (speedup 1.0000x reference)
#include <cuda_runtime.h>
#include <cuda_bf16.h>
#include <cstdint>

// input_ids (64,1024) i32 | attention_mask (64,1024) i32 | hashed_vocab (768,30000) f32
// output (64,768) f32 = L2-normalized per-row minhash signatures.
// hv[h,v] = (a_h*v + b_h) mod P, P = 30011 = next_prime(30000).
//
// Two kernels overlapped via Programmatic Dependent Launch:
//   prep_kernel  (2x384): recover (a,b) from hv[h,0..1], Fermat-invert a,
//                         publish (ainv, id0) per hash to g_par.
//   probe_kernel (128x768, PDL secondary): builds the batch's valid-token
//     byte map (param-independent prologue, runs concurrently with prep),
//     then griddepcontrol.wait, loads g_par, and probes m = 0,1,2,...:
//     smallest m with a^-1(m-b) mod P in the map (lane l checks m=32r+l,
//     ballot -> min; 16 hashes/warp, 4 chains in flight). Sibling blocks
//     (2 per batch, all co-resident) merge L2-norm partials via a
//     self-resetting global atomic handshake.
#define BATCH 64
#define SEQ   1024
#define NH    768
#define HPB   384              // hashes per block
#define TPB   768
#define HPW   16               // hashes per warp
#define VOCAB 30000
#define PRIME 30011u
#define MAPB  30016            // byte map, padded to 16B multiple

__device__ uint2    g_par[NH];        // (ainv, id0) per hash
__device__ float    g_sumsq[BATCH];   // zero-init at load; self-reset each call
__device__ unsigned g_count[BATCH];

__device__ __forceinline__ unsigned modmul(unsigned x, unsigned y) {
    return (x * y) % PRIME;    // products < 2^30; const mod -> mulhi magic
}

__global__ void __launch_bounds__(384, 1)
prep_kernel(const float* __restrict__ hv)
{
    const int t = blockIdx.x * 384 + threadIdx.x;      // 0..767
    float2 v01 = *reinterpret_cast<const float2*>(hv + (size_t)t * VOCAB);
    unsigned bb = (unsigned)v01.x;
    unsigned aa = (unsigned)v01.y + PRIME - bb;
    if (aa >= PRIME) aa -= PRIME;
    unsigned ainv = 1u, base = aa;                     // a^(P-2) mod P (Fermat)
    #pragma unroll
    for (unsigned e = PRIME - 2u; e; e >>= 1u) {
        if (e & 1u) ainv = modmul(ainv, base);
        base = modmul(base, base);
    }
    g_par[t] = make_uint2(ainv, modmul(ainv, (PRIME - bb) % PRIME));
}

__global__ void __launch_bounds__(TPB, 1)
probe_kernel(const int* __restrict__ ids,
             const int* __restrict__ mask,
             float* __restrict__ out)
{
    __shared__ uint4 pmap4[MAPB / 16];     // 30 KB byte map
    __shared__ uint2 s_par[HPB];
    __shared__ float s_red[2];             // [0]=block partial, [1]=batch total

    const int b    = blockIdx.x >> 1;
    const int half = blockIdx.x & 1;
    const int t    = threadIdx.x;
    const int lane = t & 31;
    const int warp = t >> 5;               // 0..23
    unsigned char* present = reinterpret_cast<unsigned char*>(pmap4);

    // ---- prologue (independent of prep): load tokens, zero map, scatter ----
    int idA = ids [b * SEQ + t];
    int mkA = mask[b * SEQ + t];
    int idB = 0, mkB = 0;
    if (t < SEQ - TPB) {                   // threads 0..255 cover s = 768..1023
        idB = ids [b * SEQ + TPB + t];
        mkB = mask[b * SEQ + TPB + t];
    }
    uint4 z = make_uint4(0u, 0u, 0u, 0u);
    #pragma unroll
    for (int i = t; i < MAPB / 16; i += TPB) pmap4[i] = z;
    if (t == 0) s_red[0] = 0.0f;
    __syncthreads();

    if (mkA == 1 && idA > 100 && idA < VOCAB) present[idA] = 1;
    if (mkB == 1 && idB > 100 && idB < VOCAB) present[idB] = 1;

    // ---- wait for prep's g_par (PDL), then stage params ----
    asm volatile("griddepcontrol.wait;" ::: "memory");
    if (t < HPB) s_par[t] = g_par[half * HPB + t];
    __syncthreads();

    // ---- probe: 16 hashes/warp, 4 chains in flight ----
    const int wslot = warp * HPW;
    unsigned my_m = 0u;
    #pragma unroll 1
    for (int j = 0; j < HPW / 4; ++j) {
        unsigned idl[4], stp[4], res[4];
        bool fin[4];
        #pragma unroll
        for (int k = 0; k < 4; ++k) {
            uint2 pr = s_par[wslot + j * 4 + k];        // broadcast LDS.64
            unsigned v = pr.y + (unsigned)(lane * pr.x) % PRIME;
            if (v >= PRIME) v -= PRIME;
            idl[k] = v;
            stp[k] = (pr.x << 5) % PRIME;               // 32*ainv mod P
            fin[k] = false; res[k] = 0u;
        }
        unsigned mb = 0u;
        #pragma unroll 1
        for (;;) {
            bool alldone = true;
            #pragma unroll
            for (int k = 0; k < 4; ++k) {
                unsigned bal = __ballot_sync(0xffffffffu, present[idl[k]] != 0);
                if (!fin[k]) {
                    if (bal) { res[k] = mb + (unsigned)(__ffs(bal) - 1); fin[k] = true; }
                    else alldone = false;
                }
            }
            if (alldone) break;
            #pragma unroll
            for (int k = 0; k < 4; ++k) {
                idl[k] += stp[k];
                if (idl[k] >= PRIME) idl[k] -= PRIME;
            }
            mb += 32u;
            if (mb >= (unsigned)MAPB) break;            // unreachable with real data
        }
        #pragma unroll
        for (int k = 0; k < 4; ++k)
            if (lane == j * 4 + k) my_m = res[k];       // lanes 0..15 own results
    }

    // ---- block partial of sum(m^2) ----
    float sv = (float)my_m;
    float part = (lane < HPW) ? sv * sv : 0.0f;
    #pragma unroll
    for (int o = 16; o > 0; o >>= 1)
        part += __shfl_xor_sync(0xffffffffu, part, o);
    if (lane == 0) atomicAdd(&s_red[0], part);
    __syncthreads();

    // ---- sibling-block handshake (co-resident), self-resetting ----
    if (t == 0) {
        atomicAdd(&g_sumsq[b], s_red[0]);
        __threadfence();
        atomicAdd(&g_count[b], 1u);                // arrivals: 0->1->2
        while (atomicAdd(&g_count[b], 0u) < 2u) __nanosleep(32);
        __threadfence();
        s_red[1] = atomicAdd(&g_sumsq[b], 0.0f);   // batch total
        __threadfence();
        unsigned r = atomicAdd(&g_count[b], 1u);   // read-done: 2->3->4
        if (r == 3u) {                             // last reader resets
            atomicExch(&g_sumsq[b], 0.0f);
            atomicExch(&g_count[b], 0u);
        }
    }
    __syncthreads();

    float norm = sqrtf(s_red[1]);
    if (lane < HPW)
        out[b * NH + half * HPB + wslot + lane] = sv / fmaxf(norm, 1e-12f);
}

extern "C" void kernel_launch(void* const* d_in, const int* in_sizes, int n_in,
                              void* d_out, int out_size)
{
    const int*   ids  = (const int*)d_in[0];
    const int*   mask = (const int*)d_in[1];
    const float* hv   = (const float*)d_in[2];
    float*       out  = (float*)d_out;
    (void)in_sizes; (void)n_in; (void)out_size;

    prep_kernel<<<2, 384>>>(hv);

    // PDL secondary: launches without waiting for prep; griddepcontrol.wait
    // inside the kernel provides the ordering on g_par.
    cudaLaunchConfig_t cfg = {};
    cfg.gridDim  = dim3(BATCH * 2, 1, 1);
    cfg.blockDim = dim3(TPB, 1, 1);
    cfg.dynamicSmemBytes = 0;
    cfg.stream = 0;
    cudaLaunchAttribute attr[1];
    attr[0].id = cudaLaunchAttributeProgrammaticStreamSerialization;
    attr[0].val.programmaticStreamSerializationAllowed = 1;
    cfg.attrs = attr;
    cfg.numAttrs = 1;
    cudaLaunchKernelEx(&cfg, probe_kernel, ids, mask, out);
}

// round 16
// speedup vs baseline: 1.1179x; 1.1179x over previous
#include <cuda_runtime.h>
#include <cuda_bf16.h>
#include <cstdint>

// input_ids (64,1024) i32 | attention_mask (64,1024) i32 | hashed_vocab (768,30000) f32
// output (64,768) f32 = L2-normalized per-row minhash signatures.
// hv[h,v] = (a_h*v + b_h) mod P, P = 30011 = next_prime(30000).
//
// One block per batch (grid=64, block=1024), no device-global state.
// Prologue (warp-specialized):
//   threads   0-767 : recover (a,b) from hv[h,0..1], Fermat-invert a, publish
//                     (ainv, id0, 64*ainv mod P) per hash to smem.
//   threads 768-1023: int4 ids/mask loads (256 threads = 1024 tokens), zero
//                     the 30KB valid-token byte map, named-barrier, scatter.
// Probe (all 32 warps, 24 hashes/warp, 4 chains in flight): paired probing —
// lane l checks m = 64r+2l and 64r+2l+1 (v1 = v0 + ainv); two ballots give
// the minimal m over 64 candidates per round. L2 norm is block-local.
#define BATCH 64
#define SEQ   1024
#define NH    768
#define TPB   1024
#define HPW   24               // hashes per warp (32 warps)
#define VOCAB 30000
#define PRIME 30011u
#define MAPB  30016            // byte map, padded to 16B multiple

__device__ __forceinline__ unsigned modmul(unsigned x, unsigned y) {
    return (x * y) % PRIME;    // products < 2^30; const mod -> mulhi magic
}

__global__ void __launch_bounds__(TPB, 1)
minhash_kernel(const int* __restrict__ ids,
               const int* __restrict__ mask,
               const float* __restrict__ hv,
               float* __restrict__ out)
{
    __shared__ uint4 pmap4[MAPB / 16];     // 30 KB byte map
    __shared__ uint4 s_par[NH];            // (ainv, id0, 64*ainv, -) per hash
    __shared__ float s_sumsq;

    const int b    = blockIdx.x;
    const int t    = threadIdx.x;
    const int lane = t & 31;
    const int warp = t >> 5;               // 0..31
    unsigned char* present = reinterpret_cast<unsigned char*>(pmap4);

    if (t < NH) {
        // ---- param pipeline (warps 0-23): one hash per thread ----
        float2 v01 = *reinterpret_cast<const float2*>(hv + (size_t)t * VOCAB);
        unsigned bb = (unsigned)v01.x;
        unsigned aa = (unsigned)v01.y + PRIME - bb;
        if (aa >= PRIME) aa -= PRIME;
        unsigned ainv = 1u, base = aa;               // a^(P-2) mod P (Fermat)
        #pragma unroll
        for (unsigned e = PRIME - 2u; e; e >>= 1u) {
            if (e & 1u) ainv = modmul(ainv, base);
            base = modmul(base, base);
        }
        s_par[t] = make_uint4(ainv,
                              modmul(ainv, (PRIME - bb) % PRIME),  // id at m=0
                              (ainv << 6) % PRIME,                 // 64*ainv mod P
                              0u);
        if (t == 0) s_sumsq = 0.0f;
    } else {
        // ---- map pipeline (warps 24-31): 256 threads, 4 tokens each ----
        const int tt = t - NH;                       // 0..255
        int4 idv = reinterpret_cast<const int4*>(ids  + b * SEQ)[tt];
        int4 mkv = reinterpret_cast<const int4*>(mask + b * SEQ)[tt];
        uint4 z = make_uint4(0u, 0u, 0u, 0u);
        #pragma unroll
        for (int i = tt; i < MAPB / 16; i += 256) pmap4[i] = z;
        asm volatile("bar.sync 1, 256;" ::: "memory");   // zero -> scatter order
        if (mkv.x == 1 && idv.x > 100 && idv.x < VOCAB) present[idv.x] = 1;
        if (mkv.y == 1 && idv.y > 100 && idv.y < VOCAB) present[idv.y] = 1;
        if (mkv.z == 1 && idv.z > 100 && idv.z < VOCAB) present[idv.z] = 1;
        if (mkv.w == 1 && idv.w > 100 && idv.w < VOCAB) present[idv.w] = 1;
    }
    __syncthreads();

    // ---- probe: 24 hashes/warp, 4 chains in flight, 64 candidates/round ----
    unsigned my_m = 0u;
    const int wslot = warp * HPW;
    #pragma unroll 1
    for (int j = 0; j < HPW / 4; ++j) {
        unsigned v0[4], v1[4], stp[4], res[4];
        bool fin[4];
        #pragma unroll
        for (int k = 0; k < 4; ++k) {
            uint4 pr = s_par[wslot + j * 4 + k];        // broadcast LDS.128
            unsigned a = pr.y + (unsigned)((2 * lane) * pr.x) % PRIME;
            if (a >= PRIME) a -= PRIME;                 // id at m = 2*lane
            unsigned c = a + pr.x;
            if (c >= PRIME) c -= PRIME;                 // id at m = 2*lane+1
            v0[k] = a; v1[k] = c; stp[k] = pr.z;        // advance by 64*ainv
            fin[k] = false; res[k] = 0u;
        }
        unsigned mb = 0u;
        #pragma unroll 1
        for (;;) {
            bool alldone = true;
            #pragma unroll
            for (int k = 0; k < 4; ++k) {
                unsigned p0 = present[v0[k]];
                unsigned p1 = present[v1[k]];
                unsigned b0 = __ballot_sync(0xffffffffu, p0 != 0);
                unsigned b1 = __ballot_sync(0xffffffffu, p1 != 0);
                if (!fin[k]) {
                    unsigned any = b0 | b1;
                    if (any) {
                        unsigned w = (unsigned)(__ffs(any) - 1);
                        res[k] = mb + 2u * w + (((b0 >> w) & 1u) ? 0u : 1u);
                        fin[k] = true;
                    } else {
                        alldone = false;
                        v0[k] += stp[k]; if (v0[k] >= PRIME) v0[k] -= PRIME;
                        v1[k] += stp[k]; if (v1[k] >= PRIME) v1[k] -= PRIME;
                    }
                }
            }
            if (alldone) break;
            mb += 64u;
            if (mb >= 2u * PRIME) break;                // unreachable with real data
        }
        #pragma unroll
        for (int k = 0; k < 4; ++k)
            if (lane == j * 4 + k) my_m = res[k];       // lanes 0..23 own results
    }

    // ---- block-local L2 norm over this batch's 768 signatures ----
    float sv = (float)my_m;
    float part = (lane < HPW) ? sv * sv : 0.0f;
    #pragma unroll
    for (int o = 16; o > 0; o >>= 1)
        part += __shfl_xor_sync(0xffffffffu, part, o);
    if (lane == 0) atomicAdd(&s_sumsq, part);
    __syncthreads();

    float norm = sqrtf(s_sumsq);
    if (lane < HPW)
        out[b * NH + wslot + lane] = sv / fmaxf(norm, 1e-12f);
}

extern "C" void kernel_launch(void* const* d_in, const int* in_sizes, int n_in,
                              void* d_out, int out_size)
{
    const int*   ids  = (const int*)d_in[0];
    const int*   mask = (const int*)d_in[1];
    const float* hv   = (const float*)d_in[2];
    float*       out  = (float*)d_out;
    (void)in_sizes; (void)n_in; (void)out_size;

    minhash_kernel<<<BATCH, TPB>>>(ids, mask, hv, out);
}